// round 1
// baseline (speedup 1.0000x reference)
#include <cuda_runtime.h>
#include <cuda_bf16.h>
#include <math.h>

// ---------------- problem constants ----------------
#define Bc   64
#define Nc   2048
#define Dc   256
#define Hc   64
#define NBc  3
#define Mc   (Bc * Nc)          // 131072 instances
#define KTOP 204                // int(2048*0.1)
#define K5   102                // int(2048*0.05)
#define TWOD 512
#define CATD 1280               // (2+NB)*D
#define NEG_INF_F (-1e30f)

// output layout: concatenation of the reference tuple, flattened
#define OUT_BAG   0
#define OUT_ALLA  (OUT_BAG  + Bc * TWOD)        // 32768
#define OUT_AVG   (OUT_ALLA + Bc * NBc * Nc)    // 425984
#define OUT_TOPK  (OUT_AVG  + Bc * Nc)          // 557056
#define OUT_ENT   (OUT_TOPK + Bc * Nc)          // 688128
#define OUT_EFF   (OUT_ENT  + Bc)               // 688192
#define OUT_T5    (OUT_EFF  + Bc)               // 688256

// ---------------- device scratch (no allocation allowed) ----------------
__device__ float g_Wcomb[256 * 256];     // [k][c], c: 0-63 tk scorer, 64.. branches
__device__ float g_b1c[256];
__device__ float g_w2c[256];
__device__ float g_b2c[4];
__device__ float g_scores[4L * Mc];      // [group][m]
__device__ float g_poolw[(long)Bc * 5 * Nc]; // per-batch pooling weights: mean, topk, a0,a1,a2
__device__ float g_cat[Bc * CATD];

// ---------------- helpers ----------------
__device__ __forceinline__ float tanh_fast(float x) {
    float y;
    asm("tanh.approx.f32 %0, %1;" : "=f"(y) : "f"(x));
    return y;
}
__device__ __forceinline__ unsigned f2key(float f) {
    unsigned u = __float_as_uint(f);
    return (u & 0x80000000u) ? ~u : (u | 0x80000000u);
}
__device__ __forceinline__ float key2f(unsigned k) {
    unsigned u = (k & 0x80000000u) ? (k & 0x7FFFFFFFu) : ~k;
    return __uint_as_float(u);
}

// block-of-256 reductions
__device__ __forceinline__ float blk_sum256(float v, float* red) {
    int t = threadIdx.x;
    red[t] = v; __syncthreads();
    #pragma unroll
    for (int s = 128; s > 0; s >>= 1) {
        if (t < s) red[t] += red[t + s];
        __syncthreads();
    }
    float r = red[0]; __syncthreads();
    return r;
}
__device__ __forceinline__ float blk_max256(float v, float* red) {
    int t = threadIdx.x;
    red[t] = v; __syncthreads();
    #pragma unroll
    for (int s = 128; s > 0; s >>= 1) {
        if (t < s) red[t] = fmaxf(red[t], red[t + s]);
        __syncthreads();
    }
    float r = red[0]; __syncthreads();
    return r;
}
__device__ __forceinline__ int blk_isum256(int v, int* red) {
    int t = threadIdx.x;
    red[t] = v; __syncthreads();
    #pragma unroll
    for (int s = 128; s > 0; s >>= 1) {
        if (t < s) red[t] += red[t + s];
        __syncthreads();
    }
    int r = red[0]; __syncthreads();
    return r;
}
__device__ __forceinline__ int blk_exscan256(int v, int* red) {
    int t = threadIdx.x;
    red[t] = v; __syncthreads();
    for (int s = 1; s < 256; s <<= 1) {
        int x = (t >= s) ? red[t - s] : 0;
        __syncthreads();
        red[t] += x;
        __syncthreads();
    }
    int inc = red[t];
    __syncthreads();
    return inc - v;
}

// exact K-th largest among 2048 keys (4-pass MSB radix select). 256 threads.
__device__ unsigned radix_select2048(const unsigned* keys, int K,
                                     unsigned* hist, unsigned* bc_pref, int* bc_rem) {
    int t = threadIdx.x;
    unsigned prefix = 0;
    int remaining = K;
    for (int pass = 0; pass < 4; pass++) {
        int shift = 24 - 8 * pass;
        unsigned hm = pass ? (0xFFFFFFFFu << (shift + 8)) : 0u;
        hist[t] = 0;
        __syncthreads();
        #pragma unroll
        for (int q = 0; q < 8; q++) {
            unsigned u = keys[t * 8 + q];
            if ((u & hm) == prefix) atomicAdd(&hist[(u >> shift) & 255u], 1u);
        }
        __syncthreads();
        if (t == 0) {
            int cum = 0;
            int d = 255;
            for (; d >= 0; d--) {
                cum += (int)hist[d];
                if (cum >= remaining) break;
            }
            if (d < 0) d = 0;  // defensive
            *bc_pref = prefix | ((unsigned)d << shift);
            *bc_rem = remaining - (cum - (int)hist[d]);
        }
        __syncthreads();
        prefix = *bc_pref;
        remaining = *bc_rem;
        __syncthreads();
    }
    return prefix;
}

// ---------------- K0: build combined scorer weights ----------------
__global__ void k_prep(const float* __restrict__ Ws1, const float* __restrict__ bs1,
                       const float* __restrict__ Ws2, const float* __restrict__ bs2,
                       const float* __restrict__ Wa1, const float* __restrict__ ba1,
                       const float* __restrict__ Wa2, const float* __restrict__ ba2) {
    int gid = blockIdx.x * 256 + threadIdx.x;
    if (gid < 256 * 256) {
        int k = gid >> 8, c = gid & 255;
        int g = c >> 6, ch = c & 63;
        float w = (g == 0) ? Ws1[k * Hc + ch] : Wa1[((g - 1) * Dc + k) * Hc + ch];
        g_Wcomb[k * 256 + c] = w;
    }
    if (gid < 256) {
        int g = gid >> 6, ch = gid & 63;
        g_b1c[gid] = (g == 0) ? bs1[ch] : ba1[(g - 1) * Hc + ch];
        g_w2c[gid] = (g == 0) ? Ws2[ch] : Wa2[(g - 1) * Hc + ch];
    }
    if (gid < 4) g_b2c[gid] = (gid == 0) ? bs2[0] : ba2[gid - 1];
}

// ---------------- K1: fused scorer GEMM + nonlinearity + head reduction ----------------
// M=131072 x K=256 x Ncol=256 fp32.  128x128 block tile, 8x8 thread tile, BK=16.
__global__ void __launch_bounds__(256) k_gemm_scores(const float* __restrict__ X) {
    const int m0 = blockIdx.x * 128;
    const int ct = blockIdx.y;             // 0 or 1
    const int c0 = ct * 128;
    const int tid = threadIdx.x;
    const int tx = tid & 15;
    const int ty = tid >> 4;

    __shared__ float xs[16][128];
    __shared__ float ws[16][132];

    float acc[8][8];
    #pragma unroll
    for (int i = 0; i < 8; i++)
        #pragma unroll
        for (int j = 0; j < 8; j++) acc[i][j] = 0.f;

    for (int k0 = 0; k0 < 256; k0 += 16) {
        // stage X tile (transposed)
        #pragma unroll
        for (int t = 0; t < 2; t++) {
            int idx = tid + t * 256;        // 0..511
            int i = idx >> 2;
            int kq = (idx & 3) * 4;
            float4 v = *reinterpret_cast<const float4*>(
                &X[(size_t)(m0 + i) * 256 + k0 + kq]);
            xs[kq + 0][i] = v.x;
            xs[kq + 1][i] = v.y;
            xs[kq + 2][i] = v.z;
            xs[kq + 3][i] = v.w;
        }
        // stage W tile
        #pragma unroll
        for (int t = 0; t < 2; t++) {
            int idx = tid + t * 256;
            int kk = idx >> 5;
            int cc = (idx & 31) * 4;
            float4 v = *reinterpret_cast<const float4*>(
                &g_Wcomb[(k0 + kk) * 256 + c0 + cc]);
            *reinterpret_cast<float4*>(&ws[kk][cc]) = v;
        }
        __syncthreads();
        #pragma unroll
        for (int kk = 0; kk < 16; kk++) {
            float xv[8], wv[8];
            *reinterpret_cast<float4*>(&xv[0]) = *reinterpret_cast<float4*>(&xs[kk][ty * 8]);
            *reinterpret_cast<float4*>(&xv[4]) = *reinterpret_cast<float4*>(&xs[kk][ty * 8 + 4]);
            *reinterpret_cast<float4*>(&wv[0]) = *reinterpret_cast<float4*>(&ws[kk][tx * 8]);
            *reinterpret_cast<float4*>(&wv[4]) = *reinterpret_cast<float4*>(&ws[kk][tx * 8 + 4]);
            #pragma unroll
            for (int i = 0; i < 8; i++)
                #pragma unroll
                for (int j = 0; j < 8; j++)
                    acc[i][j] += xv[i] * wv[j];
        }
        __syncthreads();
    }

    // epilogue: f(h)+dot with w2, reduce across the 8 col-threads of a 64-col group
    const int g = ct * 2 + (tx >> 3);       // group 0..3 (0 = relu scorer)
    float w2[8], b1[8];
    #pragma unroll
    for (int j = 0; j < 8; j++) {
        int c = c0 + tx * 8 + j;
        w2[j] = g_w2c[c];
        b1[j] = g_b1c[c];
    }
    const float b2 = g_b2c[g];

    #pragma unroll
    for (int i = 0; i < 8; i++) {
        float p = 0.f;
        #pragma unroll
        for (int j = 0; j < 8; j++) {
            float v = acc[i][j] + b1[j];
            float f = (g == 0) ? fmaxf(v, 0.f) : tanh_fast(v);
            p += f * w2[j];
        }
        p += __shfl_xor_sync(0xffffffff, p, 1);
        p += __shfl_xor_sync(0xffffffff, p, 2);
        p += __shfl_xor_sync(0xffffffff, p, 4);
        if ((tx & 7) == 0) {
            int m = m0 + ty * 8 + i;
            g_scores[(size_t)g * Mc + m] = p + b2;
        }
    }
}

// ---------------- K2: per-batch top-k, softmax, diagnostics, pool weights ----------------
__global__ void __launch_bounds__(256) k_perbatch(const float* __restrict__ mask,
                                                  float* __restrict__ out) {
    const int b = blockIdx.x;
    const int t = threadIdx.x;
    const int n0 = t * 8;

    __shared__ unsigned s_key[2048];
    __shared__ unsigned s_hist[256];
    __shared__ float    s_redf[256];
    __shared__ int      s_redi[256];
    __shared__ unsigned s_pref;
    __shared__ int      s_rem;

    float mk[8];
    #pragma unroll
    for (int q = 0; q < 8; q++) mk[q] = mask[b * Nc + n0 + q];

    // valid count -> mean-pool weight
    float cl = 0.f;
    #pragma unroll
    for (int q = 0; q < 8; q++) cl += mk[q];
    float cnt = blk_sum256(cl, s_redf);
    float inv_mean = 1.f / fmaxf(cnt, 1.f);

    // ---- top-k on tk scores ----
    #pragma unroll
    for (int q = 0; q < 8; q++) {
        float sc = g_scores[(size_t)b * Nc + n0 + q];
        if (mk[q] == 0.f) sc = NEG_INF_F;
        s_key[n0 + q] = f2key(sc);
    }
    __syncthreads();

    unsigned T = radix_select2048(s_key, KTOP, s_hist, &s_pref, &s_rem);

    int lg = 0, le = 0;
    #pragma unroll
    for (int q = 0; q < 8; q++) {
        unsigned u = s_key[n0 + q];
        lg += (u > T);
        le += (u == T);
    }
    int cg = blk_isum256(lg, s_redi);
    int need = KTOP - cg;
    int excl = blk_exscan256(le, s_redi);

    float tmv[8];
    float lc = 0.f;
    int rank = excl;
    #pragma unroll
    for (int q = 0; q < 8; q++) {
        unsigned u = s_key[n0 + q];
        float tm = 0.f;
        if (u > T) tm = 1.f;
        else if (u == T) { if (rank < need) tm = 1.f; rank++; }
        tmv[q] = tm;
        out[OUT_TOPK + b * Nc + n0 + q] = tm;
        lc += tm * mk[q];
    }
    float csum = blk_sum256(lc, s_redf);
    float invden = 1.f / fmaxf(csum, 1.f);
    #pragma unroll
    for (int q = 0; q < 8; q++) {
        g_poolw[((size_t)b * 5 + 0) * Nc + n0 + q] = mk[q] * inv_mean;
        g_poolw[((size_t)b * 5 + 1) * Nc + n0 + q] = tmv[q] * mk[q] * invden;
    }

    // ---- per-branch softmax ----
    float av[8] = {0.f, 0.f, 0.f, 0.f, 0.f, 0.f, 0.f, 0.f};
    for (int k = 0; k < NBc; k++) {
        float sc[8];
        float lm = -3e38f;
        #pragma unroll
        for (int q = 0; q < 8; q++) {
            float s = g_scores[(size_t)(1 + k) * Mc + b * Nc + n0 + q];
            if (mk[q] == 0.f) s = NEG_INF_F;
            sc[q] = s;
            lm = fmaxf(lm, s);
        }
        float smax = blk_max256(lm, s_redf);
        float ls = 0.f;
        #pragma unroll
        for (int q = 0; q < 8; q++) {
            sc[q] = expf(sc[q] - smax);
            ls += sc[q];
        }
        float ssum = blk_sum256(ls, s_redf);
        float inv = 1.f / ssum;
        #pragma unroll
        for (int q = 0; q < 8; q++) {
            float a = (mk[q] == 0.f) ? 0.f : sc[q] * inv;
            out[OUT_ALLA + ((size_t)b * NBc + k) * Nc + n0 + q] = a;
            g_poolw[((size_t)b * 5 + 2 + k) * Nc + n0 + q] = a;
            av[q] += a;
        }
    }
    #pragma unroll
    for (int q = 0; q < 8; q++) av[q] *= (1.f / 3.f);

    // ---- diagnostics ----
    float lent = 0.f, lsq = 0.f;
    #pragma unroll
    for (int q = 0; q < 8; q++) {
        out[OUT_AVG + b * Nc + n0 + q] = av[q];
        lent += av[q] * logf(av[q] + 1e-8f);
        lsq += av[q] * av[q];
        s_key[n0 + q] = f2key(av[q]);
    }
    float ent = blk_sum256(lent, s_redf);   // also fences s_key writes
    float sq  = blk_sum256(lsq, s_redf);
    if (t == 0) {
        out[OUT_ENT + b] = -ent;
        out[OUT_EFF + b] = 1.f / sq;
    }
    __syncthreads();

    unsigned T5 = radix_select2048(s_key, K5, s_hist, &s_pref, &s_rem);
    int lg5 = 0;
    float lsum5 = 0.f;
    #pragma unroll
    for (int q = 0; q < 8; q++) {
        unsigned u = s_key[n0 + q];
        if (u > T5) { lg5++; lsum5 += av[q]; }
    }
    int cg5 = blk_isum256(lg5, s_redi);
    float sgt = blk_sum256(lsum5, s_redf);
    if (t == 0)
        out[OUT_T5 + b] = sgt + (float)(K5 - cg5) * key2f(T5);
}

// ---------------- K3: weighted pooling (reads instances once) ----------------
__global__ void __launch_bounds__(256) k_pool(const float* __restrict__ X) {
    const int b = blockIdx.x;
    const int dt = blockIdx.y;          // 0..3 (64 dims each)
    __shared__ float sw[5][2048];       // 40KB
    __shared__ float red[4][5][64];     // 5KB

    for (int i = threadIdx.x; i < 5 * 2048; i += 256)
        (&sw[0][0])[i] = g_poolw[(size_t)b * 5 * Nc + i];
    __syncthreads();

    const int d = dt * 64 + (threadIdx.x & 63);
    const int np = threadIdx.x >> 6;    // 0..3
    float a0 = 0, a1 = 0, a2 = 0, a3 = 0, a4 = 0;
    const float* xb = X + (size_t)b * Nc * Dc;
    const int nbeg = np * 512, nend = nbeg + 512;
    for (int n = nbeg; n < nend; n++) {
        float xv = xb[(size_t)n * Dc + d];
        a0 += xv * sw[0][n];
        a1 += xv * sw[1][n];
        a2 += xv * sw[2][n];
        a3 += xv * sw[3][n];
        a4 += xv * sw[4][n];
    }
    int dd = threadIdx.x & 63;
    red[np][0][dd] = a0; red[np][1][dd] = a1; red[np][2][dd] = a2;
    red[np][3][dd] = a3; red[np][4][dd] = a4;
    __syncthreads();
    if (threadIdx.x < 64) {
        int d2 = threadIdx.x;
        #pragma unroll
        for (int p = 0; p < 5; p++) {
            float s = red[0][p][d2] + red[1][p][d2] + red[2][p][d2] + red[3][p][d2];
            g_cat[b * CATD + p * Dc + dt * 64 + d2] = s;
        }
    }
}

// ---------------- K4: fusion MLP (GEMV + LN + GELU + GEMV) ----------------
__global__ void __launch_bounds__(512) k_fuse(const float* __restrict__ Wf1,
                                              const float* __restrict__ bf1,
                                              const float* __restrict__ lng,
                                              const float* __restrict__ lnb,
                                              const float* __restrict__ Wf2,
                                              const float* __restrict__ bf2,
                                              float* __restrict__ out) {
    const int b = blockIdx.x;
    const int c = threadIdx.x;
    __shared__ float sc[CATD];
    __shared__ float sx[TWOD];
    __shared__ float red[TWOD];

    for (int i = c; i < CATD; i += TWOD) sc[i] = g_cat[b * CATD + i];
    __syncthreads();

    float acc = bf1[c];
    for (int j = 0; j < CATD; j++)
        acc += sc[j] * Wf1[j * TWOD + c];

    // LayerNorm (two-pass)
    red[c] = acc; __syncthreads();
    #pragma unroll
    for (int s = 256; s > 0; s >>= 1) {
        if (c < s) red[c] += red[c + s];
        __syncthreads();
    }
    float mu = red[0] / (float)TWOD;
    __syncthreads();
    float dv = acc - mu;
    red[c] = dv * dv; __syncthreads();
    #pragma unroll
    for (int s = 256; s > 0; s >>= 1) {
        if (c < s) red[c] += red[c + s];
        __syncthreads();
    }
    float var = red[0] / (float)TWOD;
    __syncthreads();

    float xln = dv * rsqrtf(var + 1e-5f) * lng[c] + lnb[c];
    // exact GELU (erf)
    float g = 0.5f * xln * (1.f + erff(xln * 0.70710678118654752f));
    sx[c] = g;
    __syncthreads();

    float acc2 = bf2[c];
    for (int j = 0; j < TWOD; j++)
        acc2 += sx[j] * Wf2[j * TWOD + c];
    out[OUT_BAG + b * TWOD + c] = acc2;
}

// ---------------- launch ----------------
extern "C" void kernel_launch(void* const* d_in, const int* in_sizes, int n_in,
                              void* d_out, int out_size) {
    const float* inst = (const float*)d_in[0];
    const float* mask = (const float*)d_in[1];
    const float* Ws1 = (const float*)d_in[2];
    const float* bs1 = (const float*)d_in[3];
    const float* Ws2 = (const float*)d_in[4];
    const float* bs2 = (const float*)d_in[5];
    const float* Wa1 = (const float*)d_in[6];
    const float* ba1 = (const float*)d_in[7];
    const float* Wa2 = (const float*)d_in[8];
    const float* ba2 = (const float*)d_in[9];
    const float* Wf1 = (const float*)d_in[10];
    const float* bf1 = (const float*)d_in[11];
    const float* lng = (const float*)d_in[12];
    const float* lnb = (const float*)d_in[13];
    const float* Wf2 = (const float*)d_in[14];
    const float* bf2 = (const float*)d_in[15];
    float* out = (float*)d_out;

    k_prep<<<256, 256>>>(Ws1, bs1, Ws2, bs2, Wa1, ba1, Wa2, ba2);
    k_gemm_scores<<<dim3(Mc / 128, 2), 256>>>(inst);
    k_perbatch<<<Bc, 256>>>(mask, out);
    k_pool<<<dim3(Bc, 4), 256>>>(inst);
    k_fuse<<<Bc, 512>>>(Wf1, bf1, lng, lnb, Wf2, bf2, out);
}